// round 10
// baseline (speedup 1.0000x reference)
#include <cuda_runtime.h>
#include <cuda_bf16.h>
#include <stdint.h>

#define ELEMS ((size_t)4*256*256*128)   // 33.5M

// ---------------- scratch ----------------
__device__ __align__(16) __nv_bfloat16 g_at_hi[ELEMS];
__device__ __align__(16) __nv_bfloat16 g_at_lo[ELEMS];
__device__ __align__(16) __nv_bfloat16 g_bt_hi[ELEMS];
__device__ __align__(16) __nv_bfloat16 g_bt_lo[ELEMS];
__device__ __align__(16) float g_gate[ELEMS];
__device__ __align__(16) float g_ot[ELEMS];
// pre-split weight tile images: 6 mats x (hi 34816 B + lo 34816 B), 272 B row stride
__device__ __align__(16) unsigned char g_wt[6 * 69632];

// ---------------- helpers ----------------
__device__ __forceinline__ uint32_t smem_u32(const void* p){
    uint32_t a;
    asm("{ .reg .u64 t; cvta.to.shared.u64 t, %1; cvt.u32.u64 %0, t; }" : "=r"(a) : "l"(p));
    return a;
}
__device__ __forceinline__ void ldsm_x4(uint32_t* r, uint32_t a){
    asm volatile("ldmatrix.sync.aligned.m8n8.x4.shared.b16 {%0,%1,%2,%3}, [%4];"
        : "=r"(r[0]), "=r"(r[1]), "=r"(r[2]), "=r"(r[3]) : "r"(a));
}
__device__ __forceinline__ void mma16816(float* c, const uint32_t* a, const uint32_t* b){
    asm volatile("mma.sync.aligned.m16n8k16.row.col.f32.bf16.bf16.f32 "
        "{%0,%1,%2,%3}, {%4,%5,%6,%7}, {%8,%9}, {%0,%1,%2,%3};"
        : "+f"(c[0]), "+f"(c[1]), "+f"(c[2]), "+f"(c[3])
        : "r"(a[0]), "r"(a[1]), "r"(a[2]), "r"(a[3]), "r"(b[0]), "r"(b[1]));
}
__device__ __forceinline__ void cp16(uint32_t dst, const void* src){
    asm volatile("cp.async.cg.shared.global [%0], [%1], 16;" :: "r"(dst), "l"(src));
}
__device__ __forceinline__ void cp_commit(){
    asm volatile("cp.async.commit_group;" ::: "memory");
}
__device__ __forceinline__ void cp_wait0(){
    asm volatile("cp.async.wait_group 0;" ::: "memory");
}
__device__ __forceinline__ float sigmoidf_(float x){ return 1.0f / (1.0f + __expf(-x)); }
__device__ __forceinline__ uint16_t bf16bits(float v){
    __nv_bfloat16 h = __float2bfloat16(v);
    return *reinterpret_cast<uint16_t*>(&h);
}
__device__ __forceinline__ float bf2f(uint16_t u){
    __nv_bfloat16 h = *reinterpret_cast<__nv_bfloat16*>(&u);
    return __bfloat162float(h);
}
__device__ __forceinline__ void split4(float4 v, uint2& hh, uint2& ll){
    uint16_t h0=bf16bits(v.x), h1=bf16bits(v.y), h2=bf16bits(v.z), h3=bf16bits(v.w);
    uint16_t l0=bf16bits(v.x-bf2f(h0)), l1=bf16bits(v.y-bf2f(h1)),
             l2=bf16bits(v.z-bf2f(h2)), l3=bf16bits(v.w-bf2f(h3));
    hh.x = (uint32_t)h0 | ((uint32_t)h1<<16); hh.y = (uint32_t)h2 | ((uint32_t)h3<<16);
    ll.x = (uint32_t)l0 | ((uint32_t)l1<<16); ll.y = (uint32_t)l2 | ((uint32_t)l3<<16);
}

#define TSTRIDE 272u   // full-K (128) bf16 tile row stride in bytes
#define HSTRIDE 144u   // half-K (64)  bf16 tile row stride in bytes

// 32x32 warp-tile split GEMM over 64 K (4 ksteps). acc[2 m-subtiles][4 n-octets][4].
template<int SA, int SB>
__device__ __forceinline__ void gemm32(float (&acc)[2][4][4],
    uint32_t aHi, uint32_t aLo, uint32_t bHi, uint32_t bLo, int lane)
{
    const uint32_t aOff = (uint32_t)(lane & 15) * SA + (uint32_t)((lane >> 4) << 4);
    const uint32_t bOff = (uint32_t)(((lane >> 4) << 3) + (lane & 7)) * SB
                        + (uint32_t)(((lane >> 3) & 1) << 4);
    #pragma unroll
    for (int ks = 0; ks < 4; ks++) {
        const uint32_t ka = aOff + (uint32_t)ks * 32u;
        const uint32_t kb = bOff + (uint32_t)ks * 32u;
        uint32_t ah[2][4], al[2][4], bb[2][4];
        ldsm_x4(ah[0], aHi + ka);
        ldsm_x4(ah[1], aHi + 16u * SA + ka);
        ldsm_x4(bb[0], bHi + kb);
        ldsm_x4(bb[1], bHi + 16u * SB + kb);
        #pragma unroll
        for (int mt = 0; mt < 2; mt++)
            #pragma unroll
            for (int q = 0; q < 4; q++)
                mma16816(acc[mt][q], ah[mt], &bb[q >> 1][(q & 1) << 1]);
        ldsm_x4(al[0], aLo + ka);
        ldsm_x4(al[1], aLo + 16u * SA + ka);
        #pragma unroll
        for (int mt = 0; mt < 2; mt++)
            #pragma unroll
            for (int q = 0; q < 4; q++)
                mma16816(acc[mt][q], al[mt], &bb[q >> 1][(q & 1) << 1]);
        ldsm_x4(bb[0], bLo + kb);
        ldsm_x4(bb[1], bLo + 16u * SB + kb);
        #pragma unroll
        for (int mt = 0; mt < 2; mt++)
            #pragma unroll
            for (int q = 0; q < 4; q++)
                mma16816(acc[mt][q], ah[mt], &bb[q >> 1][(q & 1) << 1]);
    }
}

// async copy one half-K (64k) weight tile image (hi + lo planes). NT = blockDim.
template<int NT>
__device__ __forceinline__ void load_w_half(uint32_t dst, int mat, int half){
    const unsigned char* src = g_wt + (size_t)mat * 69632 + half * 128;
    #pragma unroll
    for (int it = 0; it < 2048 / NT; it++) {
        int lin = threadIdx.x + it * NT;       // 0..2047
        int plane = lin >> 10, idx = lin & 1023;
        int r = idx >> 3, c = idx & 7;
        cp16(dst + (uint32_t)plane * 18432u + (uint32_t)r * HSTRIDE + (uint32_t)c * 16u,
             src + (size_t)plane * 34816 + (size_t)r * 272 + c * 16);
    }
    cp_commit();
}

// LN one row (128 cols) by a full warp; write split bf16 into A tile (272B stride).
__device__ __forceinline__ void ln_row(char* smp, uint32_t hiOff, uint32_t loOff,
    int row, int lane, const float* x,
    float g0, float g1, float g2, float g3,
    float c0, float c1, float c2, float c3)
{
    float v0 = x[lane], v1 = x[lane+32], v2 = x[lane+64], v3 = x[lane+96];
    float s = v0 + v1 + v2 + v3;
    #pragma unroll
    for (int o = 16; o > 0; o >>= 1) s += __shfl_xor_sync(0xffffffffu, s, o);
    float mean = s * (1.0f / 128.0f);
    float d0 = v0-mean, d1 = v1-mean, d2 = v2-mean, d3 = v3-mean;
    float q = d0*d0 + d1*d1 + d2*d2 + d3*d3;
    #pragma unroll
    for (int o = 16; o > 0; o >>= 1) q += __shfl_xor_sync(0xffffffffu, q, o);
    float inv = rsqrtf(q * (1.0f / 128.0f) + 1e-5f);
    float y0 = d0*inv*g0 + c0, y1 = d1*inv*g1 + c1;
    float y2 = d2*inv*g2 + c2, y3 = d3*inv*g3 + c3;
    uint16_t* aH = (uint16_t*)(smp + hiOff);
    uint16_t* aL = (uint16_t*)(smp + loOff);
    uint16_t h;
    h = bf16bits(y0); aH[row*136 + lane]      = h; aL[row*136 + lane]      = bf16bits(y0 - bf2f(h));
    h = bf16bits(y1); aH[row*136 + lane + 32] = h; aL[row*136 + lane + 32] = bf16bits(y1 - bf2f(h));
    h = bf16bits(y2); aH[row*136 + lane + 64] = h; aL[row*136 + lane + 64] = bf16bits(y2 - bf2f(h));
    h = bf16bits(y3); aH[row*136 + lane + 96] = h; aL[row*136 + lane + 96] = bf16bits(y3 - bf2f(h));
}

// ============================================================
// Kernel W: pre-split the 6 weight matrices (0=wga 1=wpa 2=wgb 3=wpb 4=wog 5=wop)
// ============================================================
__global__ void __launch_bounds__(512, 1) prep_w_kernel(
    const float* __restrict__ wga, const float* __restrict__ wpa,
    const float* __restrict__ wgb, const float* __restrict__ wpb,
    const float* __restrict__ wog, const float* __restrict__ wop)
{
    const float* Ws[6] = {wga, wpa, wgb, wpb, wog, wop};
    const float* W = Ws[blockIdx.x];
    unsigned char* dst = g_wt + (size_t)blockIdx.x * 69632;
    #pragma unroll
    for (int it = 0; it < 8; it++) {
        int lin = threadIdx.x + it * 512;
        int r = lin >> 5, c4 = (lin & 31) << 2;
        float4 v = *(const float4*)(W + r * 128 + c4);
        uint2 hh, ll;
        split4(v, hh, ll);
        *(uint2*)(dst + r * TSTRIDE + c4 * 2) = hh;
        *(uint2*)(dst + 34816 + r * TSTRIDE + c4 * 2) = ll;
    }
}

// ============================================================
// Kernel P: LN(z) + 5 projections.  128 rows, 512 threads (16 warps 4x4), 1 CTA/SM.
// smem: A_hi 0 (34816), A_lo 34816, WB0 69632 (36864), WB1 106496 (36864) = 143360.
// Pair epilogue stages into [69632..139264) (both W buffers).
// ============================================================
#define PR_AHI 0u
#define PR_ALO 34816u
#define PR_WB0 69632u
#define PR_WB1 106496u
#define PR_ST  69632u
#define PR_SMEM 143360

__global__ void __launch_bounds__(512, 1) proj_kernel(
    const float* __restrict__ z, const float* __restrict__ gin, const float* __restrict__ bin,
    const float* __restrict__ bga, const float* __restrict__ bpa,
    const float* __restrict__ bgb, const float* __restrict__ bpb,
    const float* __restrict__ bog)
{
    extern __shared__ char smp[];
    const uint32_t sb = smem_u32(smp);
    const int tid = threadIdx.x, wid = tid >> 5, lane = tid & 31;

    const size_t m0 = (size_t)blockIdx.x * 128;
    const int b  = (int)(m0 >> 16);
    const int ii = (int)((m0 >> 8) & 255);
    const int k0 = (int)(m0 & 255);

    load_w_half<512>(sb + PR_WB0, 0, 0);            // wga h0, hidden behind LN

    {   // LN rows -> split A tiles (8 rows per warp)
        const float g0 = gin[lane], g1 = gin[lane+32], g2 = gin[lane+64], g3 = gin[lane+96];
        const float c0 = bin[lane], c1 = bin[lane+32], c2 = bin[lane+64], c3 = bin[lane+96];
        #pragma unroll
        for (int r = 0; r < 8; r++) {
            int row = wid * 8 + r;
            ln_row(smp, PR_AHI, PR_ALO, row, lane, z + (m0 + row) * 128,
                   g0, g1, g2, g3, c0, c1, c2, c3);
        }
    }
    cp_wait0(); __syncthreads();

    const int m0w = (wid >> 2) * 32, n0w = (wid & 3) * 32;
    const uint32_t aH0 = sb + PR_AHI + (uint32_t)m0w * TSTRIDE;
    const uint32_t aL0 = sb + PR_ALO + (uint32_t)m0w * TSTRIDE;
    const uint32_t b0n = sb + PR_WB0 + (uint32_t)n0w * HSTRIDE;
    const uint32_t b1n = sb + PR_WB1 + (uint32_t)n0w * HSTRIDE;

    // ---- two gated-pair phases (invariant at entry: WB0 = (gmat, h0), no cp pending) ----
    for (int ph = 0; ph < 2; ph++) {
        const int gmat = ph ? 2 : 0, pmat = ph ? 3 : 1;
        const float* bg = ph ? bgb : bga;
        const float* bp = ph ? bpb : bpa;

        float accG[2][4][4] = {}, accP[2][4][4] = {};

        load_w_half<512>(sb + PR_WB1, gmat, 1);
        gemm32<TSTRIDE, HSTRIDE>(accG, aH0, aL0, b0n, b0n + 18432u, lane);
        cp_wait0(); __syncthreads();

        load_w_half<512>(sb + PR_WB0, pmat, 0);
        gemm32<TSTRIDE, HSTRIDE>(accG, aH0 + 128u, aL0 + 128u, b1n, b1n + 18432u, lane);
        cp_wait0(); __syncthreads();

        load_w_half<512>(sb + PR_WB1, pmat, 1);
        gemm32<TSTRIDE, HSTRIDE>(accP, aH0, aL0, b0n, b0n + 18432u, lane);
        cp_wait0(); __syncthreads();

        gemm32<TSTRIDE, HSTRIDE>(accP, aH0 + 128u, aL0 + 128u, b1n, b1n + 18432u, lane);
        __syncthreads();

        // stage transposed: stH/stL [d 128][m 136] bf16 over both W buffers
        uint16_t* stH = (uint16_t*)(smp + PR_ST);
        uint16_t* stL = (uint16_t*)(smp + PR_ST + 34816u);
        #pragma unroll
        for (int mt = 0; mt < 2; mt++)
            #pragma unroll
            for (int q = 0; q < 4; q++) {
                int n = n0w + q * 8 + 2 * (lane & 3);
                float2 bg2 = *(const float2*)(bg + n);
                float2 bp2 = *(const float2*)(bp + n);
                #pragma unroll
                for (int rh = 0; rh < 2; rh++) {
                    int m = m0w + mt * 16 + (lane >> 2) + rh * 8;
                    float v0 = sigmoidf_(accG[mt][q][rh*2]   + bg2.x) * (accP[mt][q][rh*2]   + bp2.x);
                    float v1 = sigmoidf_(accG[mt][q][rh*2+1] + bg2.y) * (accP[mt][q][rh*2+1] + bp2.y);
                    uint16_t h0 = bf16bits(v0), h1 = bf16bits(v1);
                    stH[n * 136 + m]       = h0;  stL[n * 136 + m]       = bf16bits(v0 - bf2f(h0));
                    stH[(n + 1) * 136 + m] = h1;  stL[(n + 1) * 136 + m] = bf16bits(v1 - bf2f(h1));
                }
            }
        __syncthreads();

        __nv_bfloat16* dH = ph ? g_bt_hi : g_at_hi;
        __nv_bfloat16* dL = ph ? g_bt_lo : g_at_lo;
        #pragma unroll
        for (int it = 0; it < 8; it++) {
            int lin = tid + it * 512;               // 0..4095
            int hl  = lin >> 11;
            int idx = lin & 2047;
            int d = idx >> 4, m8 = (idx & 15) << 3;
            uint4 v = *(const uint4*)(smp + PR_ST + (uint32_t)hl * 34816u + d * TSTRIDE + m8 * 2);
            __nv_bfloat16* dst = hl ? dL : dH;
            *(uint4*)(dst + ((size_t)(b * 128 + d)) * 65536 + (size_t)ii * 256 + k0 + m8) = v;
        }
        __syncthreads();                            // stage fully consumed
        load_w_half<512>(sb + PR_WB0, ph ? 4 : 2, 0);  // next G.h0 (or wog.h0)
        cp_wait0(); __syncthreads();
    }

    // ---- gate phase (WB0 = wog h0) ----
    float acc[2][4][4] = {};
    load_w_half<512>(sb + PR_WB1, 4, 1);
    gemm32<TSTRIDE, HSTRIDE>(acc, aH0, aL0, b0n, b0n + 18432u, lane);
    cp_wait0(); __syncthreads();
    gemm32<TSTRIDE, HSTRIDE>(acc, aH0 + 128u, aL0 + 128u, b1n, b1n + 18432u, lane);

    #pragma unroll
    for (int mt = 0; mt < 2; mt++)
        #pragma unroll
        for (int q = 0; q < 4; q++) {
            int n = n0w + q * 8 + 2 * (lane & 3);
            float2 bo2 = *(const float2*)(bog + n);
            #pragma unroll
            for (int rh = 0; rh < 2; rh++) {
                int m = m0w + mt * 16 + (lane >> 2) + rh * 8;
                float2 o;
                o.x = sigmoidf_(acc[mt][q][rh*2]   + bo2.x);
                o.y = sigmoidf_(acc[mt][q][rh*2+1] + bo2.y);
                *(float2*)(g_gate + (m0 + m) * 128 + n) = o;
            }
        }
}

// ============================================================
// Kernel T: triangle einsum. C tile 64x128, 256 threads (8 warps), 2 CTAs/SM.
// K = 256 in 4 chunks of 64, double-buffered (2 x 55296 = 110592 B).
// grid.x = 4096: bd = bx>>3, i0 = ((bx>>1)&3)*64, j0 = (bx&1)*128
// ============================================================
#define TR_BUFSZ 55296u
#define TR_SMEM  110592

__device__ __forceinline__ void tri_load_chunk(uint32_t bufBase, size_t base,
                                               int i0, int j0, int kc)
{
    #pragma unroll
    for (int it = 0; it < 12; it++) {
        int lin = threadIdx.x + it * 256;          // 0..3071
        if (lin < 1024) {                          // A: 64 rows, hi/lo
            int plane = lin >> 9, idx = lin & 511;
            int r = idx >> 3, c = idx & 7;
            const __nv_bfloat16* s = plane ? g_at_lo : g_at_hi;
            cp16(bufBase + (uint32_t)plane * 9216u + (uint32_t)r * HSTRIDE + (uint32_t)c * 16u,
                 s + base + (size_t)(i0 + r) * 256 + kc * 64 + c * 8);
        } else {                                   // B: 128 rows, hi/lo
            int l2 = lin - 1024;
            int plane = l2 >> 10, idx = l2 & 1023;
            int r = idx >> 3, c = idx & 7;
            const __nv_bfloat16* s = plane ? g_bt_lo : g_bt_hi;
            cp16(bufBase + 18432u + (uint32_t)plane * 18432u + (uint32_t)r * HSTRIDE + (uint32_t)c * 16u,
                 s + base + (size_t)(j0 + r) * 256 + kc * 64 + c * 8);
        }
    }
    cp_commit();
}

__global__ void __launch_bounds__(256, 2) tri_kernel()
{
    extern __shared__ char smp[];
    const uint32_t sb = smem_u32(smp);
    const int tid = threadIdx.x, wid = tid >> 5, lane = tid & 31;
    const int bx = blockIdx.x;
    const int bd = bx >> 3;
    const int i0 = ((bx >> 1) & 3) * 64;
    const int j0 = (bx & 1) * 128;
    const size_t base = (size_t)bd * 65536;

    const int m0w = (wid >> 2) * 32, n0w = (wid & 3) * 32;
    float acc[2][4][4] = {};

    tri_load_chunk(sb, base, i0, j0, 0);
    #pragma unroll
    for (int kc = 0; kc < 4; kc++) {
        cp_wait0(); __syncthreads();
        if (kc < 3) tri_load_chunk(sb + ((kc + 1) & 1) * TR_BUFSZ, base, i0, j0, kc + 1);
        const uint32_t bf = sb + (kc & 1) * TR_BUFSZ;
        gemm32<HSTRIDE, HSTRIDE>(acc,
            bf + (uint32_t)m0w * HSTRIDE, bf + 9216u + (uint32_t)m0w * HSTRIDE,
            bf + 18432u + (uint32_t)n0w * HSTRIDE, bf + 36864u + (uint32_t)n0w * HSTRIDE, lane);
    }

    #pragma unroll
    for (int mt = 0; mt < 2; mt++)
        #pragma unroll
        for (int q = 0; q < 4; q++) {
            int n = n0w + q * 8 + 2 * (lane & 3);
            #pragma unroll
            for (int rh = 0; rh < 2; rh++) {
                int m = m0w + mt * 16 + (lane >> 2) + rh * 8;
                float2 o = make_float2(acc[mt][q][rh*2], acc[mt][q][rh*2+1]);
                *(float2*)(g_ot + base + (size_t)(i0 + m) * 256 + j0 + n) = o;
            }
        }
}

// ============================================================
// Kernel F: transpose-gather + LN + wop + gate.  64 p-rows, 256 threads, 3 CTAs/SM.
// smem: A_hi 0, A_lo 17408; X f32 [64][133] @34816 (dead after LN);
//       W halves overlay X: whi 34816, wlo 53248.  Total 71680.
// grid.x = 4096: b = bx>>10, p0 = (bx&1023)*64
// ============================================================
#define FN_AHI 0u
#define FN_ALO 17408u
#define FN_X   34816u
#define FN_W   34816u
#define FN_SMEM 71680

__global__ void __launch_bounds__(256, 3) final_kernel(
    const float* __restrict__ gout, const float* __restrict__ bout,
    const float* __restrict__ bop, float* __restrict__ outp)
{
    extern __shared__ char smp[];
    const uint32_t sb = smem_u32(smp);
    const int tid = threadIdx.x, wid = tid >> 5, lane = tid & 31;
    const int b  = blockIdx.x >> 10;
    const int p0 = (blockIdx.x & 1023) * 64;

    // gather-transpose: X[p][d] <- g_ot[b][d][p0+p]
    float* X = (float*)(smp + FN_X);
    #pragma unroll
    for (int it = 0; it < 8; it++) {
        int lin = tid + it * 256;
        int d = lin >> 4, p4 = (lin & 15) << 2;
        float4 v = *(const float4*)(g_ot + ((size_t)(b * 128 + d)) * 65536 + p0 + p4);
        X[(p4 + 0) * 133 + d] = v.x;
        X[(p4 + 1) * 133 + d] = v.y;
        X[(p4 + 2) * 133 + d] = v.z;
        X[(p4 + 3) * 133 + d] = v.w;
    }
    __syncthreads();

    // LN rows of X -> split A tiles (8 rows per warp)
    {
        const float g0 = gout[lane], g1 = gout[lane+32], g2 = gout[lane+64], g3 = gout[lane+96];
        const float c0 = bout[lane], c1 = bout[lane+32], c2 = bout[lane+64], c3 = bout[lane+96];
        #pragma unroll
        for (int r = 0; r < 8; r++) {
            int row = wid * 8 + r;
            ln_row(smp, FN_AHI, FN_ALO, row, lane, X + row * 133,
                   g0, g1, g2, g3, c0, c1, c2, c3);
        }
    }
    __syncthreads();            // X fully consumed before W overlays it

    const int m0w = (wid >> 2) * 32, n0w = (wid & 3) * 32;
    const uint32_t aH0 = sb + FN_AHI + (uint32_t)m0w * TSTRIDE;
    const uint32_t aL0 = sb + FN_ALO + (uint32_t)m0w * TSTRIDE;
    const uint32_t wn  = sb + FN_W + (uint32_t)n0w * HSTRIDE;

    float acc[2][4][4] = {};
    load_w_half<256>(sb + FN_W, 5, 0);
    cp_wait0(); __syncthreads();
    gemm32<TSTRIDE, HSTRIDE>(acc, aH0, aL0, wn, wn + 18432u, lane);
    __syncthreads();
    load_w_half<256>(sb + FN_W, 5, 1);
    cp_wait0(); __syncthreads();
    gemm32<TSTRIDE, HSTRIDE>(acc, aH0 + 128u, aL0 + 128u, wn, wn + 18432u, lane);

    #pragma unroll
    for (int mt = 0; mt < 2; mt++)
        #pragma unroll
        for (int q = 0; q < 4; q++) {
            int n = n0w + q * 8 + 2 * (lane & 3);
            float2 bo2 = *(const float2*)(bop + n);
            #pragma unroll
            for (int rh = 0; rh < 2; rh++) {
                int m = m0w + mt * 16 + (lane >> 2) + rh * 8;
                size_t gi = ((size_t)b * 65536 + p0 + m) * 128 + n;
                float2 g = *(const float2*)(g_gate + gi);
                float2 o;
                o.x = g.x * (acc[mt][q][rh*2]   + bo2.x);
                o.y = g.y * (acc[mt][q][rh*2+1] + bo2.y);
                *(float2*)(outp + gi) = o;
            }
        }
}

// ============================================================
// launch
// ============================================================
extern "C" void kernel_launch(void* const* d_in, const int* in_sizes, int n_in,
                              void* d_out, int out_size)
{
    const float* z    = (const float*)d_in[0];
    const float* gin  = (const float*)d_in[1];
    const float* bin  = (const float*)d_in[2];
    const float* wpa  = (const float*)d_in[3];
    const float* bpa  = (const float*)d_in[4];
    const float* wga  = (const float*)d_in[5];
    const float* bga  = (const float*)d_in[6];
    const float* wpb  = (const float*)d_in[7];
    const float* bpb  = (const float*)d_in[8];
    const float* wgb  = (const float*)d_in[9];
    const float* bgb  = (const float*)d_in[10];
    const float* gout = (const float*)d_in[11];
    const float* bout = (const float*)d_in[12];
    const float* wop  = (const float*)d_in[13];
    const float* bop  = (const float*)d_in[14];
    const float* wog  = (const float*)d_in[15];
    const float* bog  = (const float*)d_in[16];
    float* outp = (float*)d_out;

    cudaFuncSetAttribute(proj_kernel,  cudaFuncAttributeMaxDynamicSharedMemorySize, PR_SMEM);
    cudaFuncSetAttribute(tri_kernel,   cudaFuncAttributeMaxDynamicSharedMemorySize, TR_SMEM);
    cudaFuncSetAttribute(final_kernel, cudaFuncAttributeMaxDynamicSharedMemorySize, FN_SMEM);

    prep_w_kernel<<<6, 512>>>(wga, wpa, wgb, wpb, wog, wop);
    proj_kernel<<<2048, 512, PR_SMEM>>>(z, gin, bin, bga, bpa, bgb, bpb, bog);
    tri_kernel<<<4096, 256, TR_SMEM>>>();
    final_kernel<<<4096, 256, FN_SMEM>>>(gout, bout, bop, outp);
}

// round 11
// speedup vs baseline: 1.0547x; 1.0547x over previous
#include <cuda_runtime.h>
#include <cuda_bf16.h>
#include <stdint.h>

#define ELEMS ((size_t)4*256*256*128)   // 33.5M

// ---------------- scratch ----------------
__device__ __align__(16) __nv_bfloat16 g_at_hi[ELEMS];
__device__ __align__(16) __nv_bfloat16 g_at_lo[ELEMS];
__device__ __align__(16) __nv_bfloat16 g_bt_hi[ELEMS];
__device__ __align__(16) __nv_bfloat16 g_bt_lo[ELEMS];
__device__ __align__(16) float g_gate[ELEMS];
__device__ __align__(16) float g_ot[ELEMS];
// pre-split weight tile images: 6 mats x (hi 34816 B + lo 34816 B), 272 B row stride
__device__ __align__(16) unsigned char g_wt[6 * 69632];

// ---------------- helpers ----------------
__device__ __forceinline__ uint32_t smem_u32(const void* p){
    uint32_t a;
    asm("{ .reg .u64 t; cvta.to.shared.u64 t, %1; cvt.u32.u64 %0, t; }" : "=r"(a) : "l"(p));
    return a;
}
__device__ __forceinline__ void ldsm_x4(uint32_t* r, uint32_t a){
    asm volatile("ldmatrix.sync.aligned.m8n8.x4.shared.b16 {%0,%1,%2,%3}, [%4];"
        : "=r"(r[0]), "=r"(r[1]), "=r"(r[2]), "=r"(r[3]) : "r"(a));
}
__device__ __forceinline__ void mma16816(float* c, const uint32_t* a, const uint32_t* b){
    asm volatile("mma.sync.aligned.m16n8k16.row.col.f32.bf16.bf16.f32 "
        "{%0,%1,%2,%3}, {%4,%5,%6,%7}, {%8,%9}, {%0,%1,%2,%3};"
        : "+f"(c[0]), "+f"(c[1]), "+f"(c[2]), "+f"(c[3])
        : "r"(a[0]), "r"(a[1]), "r"(a[2]), "r"(a[3]), "r"(b[0]), "r"(b[1]));
}
__device__ __forceinline__ void cp16(uint32_t dst, const void* src){
    asm volatile("cp.async.cg.shared.global [%0], [%1], 16;" :: "r"(dst), "l"(src));
}
__device__ __forceinline__ void cp_commit(){
    asm volatile("cp.async.commit_group;" ::: "memory");
}
__device__ __forceinline__ void cp_wait0(){
    asm volatile("cp.async.wait_group 0;" ::: "memory");
}
__device__ __forceinline__ float sigmoidf_(float x){ return 1.0f / (1.0f + __expf(-x)); }
__device__ __forceinline__ uint16_t bf16bits(float v){
    __nv_bfloat16 h = __float2bfloat16(v);
    return *reinterpret_cast<uint16_t*>(&h);
}
__device__ __forceinline__ float bf2f(uint16_t u){
    __nv_bfloat16 h = *reinterpret_cast<__nv_bfloat16*>(&u);
    return __bfloat162float(h);
}
__device__ __forceinline__ void split4(float4 v, uint2& hh, uint2& ll){
    uint16_t h0=bf16bits(v.x), h1=bf16bits(v.y), h2=bf16bits(v.z), h3=bf16bits(v.w);
    uint16_t l0=bf16bits(v.x-bf2f(h0)), l1=bf16bits(v.y-bf2f(h1)),
             l2=bf16bits(v.z-bf2f(h2)), l3=bf16bits(v.w-bf2f(h3));
    hh.x = (uint32_t)h0 | ((uint32_t)h1<<16); hh.y = (uint32_t)h2 | ((uint32_t)h3<<16);
    ll.x = (uint32_t)l0 | ((uint32_t)l1<<16); ll.y = (uint32_t)l2 | ((uint32_t)l3<<16);
}

#define TSTRIDE 272u   // full-K (128) bf16 tile row stride in bytes
#define HSTRIDE 144u   // half-K (64)  bf16 tile row stride in bytes

// 32x32 warp-tile split GEMM over 64 K (4 ksteps). acc[2 m-subtiles][4 n-octets][4].
template<int SA, int SB>
__device__ __forceinline__ void gemm32(float (&acc)[2][4][4],
    uint32_t aHi, uint32_t aLo, uint32_t bHi, uint32_t bLo, int lane)
{
    const uint32_t aOff = (uint32_t)(lane & 15) * SA + (uint32_t)((lane >> 4) << 4);
    const uint32_t bOff = (uint32_t)(((lane >> 4) << 3) + (lane & 7)) * SB
                        + (uint32_t)(((lane >> 3) & 1) << 4);
    #pragma unroll
    for (int ks = 0; ks < 4; ks++) {
        const uint32_t ka = aOff + (uint32_t)ks * 32u;
        const uint32_t kb = bOff + (uint32_t)ks * 32u;
        uint32_t ah[2][4], al[2][4], bb[2][4];
        ldsm_x4(ah[0], aHi + ka);
        ldsm_x4(ah[1], aHi + 16u * SA + ka);
        ldsm_x4(bb[0], bHi + kb);
        ldsm_x4(bb[1], bHi + 16u * SB + kb);
        #pragma unroll
        for (int mt = 0; mt < 2; mt++)
            #pragma unroll
            for (int q = 0; q < 4; q++)
                mma16816(acc[mt][q], ah[mt], &bb[q >> 1][(q & 1) << 1]);
        ldsm_x4(al[0], aLo + ka);
        ldsm_x4(al[1], aLo + 16u * SA + ka);
        #pragma unroll
        for (int mt = 0; mt < 2; mt++)
            #pragma unroll
            for (int q = 0; q < 4; q++)
                mma16816(acc[mt][q], al[mt], &bb[q >> 1][(q & 1) << 1]);
        ldsm_x4(bb[0], bLo + kb);
        ldsm_x4(bb[1], bLo + 16u * SB + kb);
        #pragma unroll
        for (int mt = 0; mt < 2; mt++)
            #pragma unroll
            for (int q = 0; q < 4; q++)
                mma16816(acc[mt][q], ah[mt], &bb[q >> 1][(q & 1) << 1]);
    }
}

// async copy one half-K (64k) weight tile (hi + lo planes), 256-thread blocks
__device__ __forceinline__ void load_w_half(uint32_t dst, int mat, int half){
    const unsigned char* src = g_wt + (size_t)mat * 69632 + half * 128;
    #pragma unroll
    for (int it = 0; it < 8; it++) {
        int lin = threadIdx.x + it * 256;      // 0..2047
        int plane = lin >> 10, idx = lin & 1023;
        int r = idx >> 3, c = idx & 7;
        cp16(dst + (uint32_t)plane * 18432u + (uint32_t)r * HSTRIDE + (uint32_t)c * 16u,
             src + (size_t)plane * 34816 + (size_t)r * 272 + c * 16);
    }
    cp_commit();
}

// LN one row (128 cols) by a full warp; write split bf16 into A tile (272B stride).
__device__ __forceinline__ void ln_row(char* smp, uint32_t hiOff, uint32_t loOff,
    int row, int lane, const float* x,
    float g0, float g1, float g2, float g3,
    float c0, float c1, float c2, float c3)
{
    float v0 = x[lane], v1 = x[lane+32], v2 = x[lane+64], v3 = x[lane+96];
    float s = v0 + v1 + v2 + v3;
    #pragma unroll
    for (int o = 16; o > 0; o >>= 1) s += __shfl_xor_sync(0xffffffffu, s, o);
    float mean = s * (1.0f / 128.0f);
    float d0 = v0-mean, d1 = v1-mean, d2 = v2-mean, d3 = v3-mean;
    float q = d0*d0 + d1*d1 + d2*d2 + d3*d3;
    #pragma unroll
    for (int o = 16; o > 0; o >>= 1) q += __shfl_xor_sync(0xffffffffu, q, o);
    float inv = rsqrtf(q * (1.0f / 128.0f) + 1e-5f);
    float y0 = d0*inv*g0 + c0, y1 = d1*inv*g1 + c1;
    float y2 = d2*inv*g2 + c2, y3 = d3*inv*g3 + c3;
    uint16_t* aH = (uint16_t*)(smp + hiOff);
    uint16_t* aL = (uint16_t*)(smp + loOff);
    uint16_t h;
    h = bf16bits(y0); aH[row*136 + lane]      = h; aL[row*136 + lane]      = bf16bits(y0 - bf2f(h));
    h = bf16bits(y1); aH[row*136 + lane + 32] = h; aL[row*136 + lane + 32] = bf16bits(y1 - bf2f(h));
    h = bf16bits(y2); aH[row*136 + lane + 64] = h; aL[row*136 + lane + 64] = bf16bits(y2 - bf2f(h));
    h = bf16bits(y3); aH[row*136 + lane + 96] = h; aL[row*136 + lane + 96] = bf16bits(y3 - bf2f(h));
}

// ============================================================
// Kernel W: pre-split the 6 weight matrices (0=wga 1=wpa 2=wgb 3=wpb 4=wog 5=wop)
// ============================================================
__global__ void __launch_bounds__(512, 1) prep_w_kernel(
    const float* __restrict__ wga, const float* __restrict__ wpa,
    const float* __restrict__ wgb, const float* __restrict__ wpb,
    const float* __restrict__ wog, const float* __restrict__ wop)
{
    const float* Ws[6] = {wga, wpa, wgb, wpb, wog, wop};
    const float* W = Ws[blockIdx.x];
    unsigned char* dst = g_wt + (size_t)blockIdx.x * 69632;
    #pragma unroll
    for (int it = 0; it < 8; it++) {
        int lin = threadIdx.x + it * 512;
        int r = lin >> 5, c4 = (lin & 31) << 2;
        float4 v = *(const float4*)(W + r * 128 + c4);
        uint2 hh, ll;
        split4(v, hh, ll);
        *(uint2*)(dst + r * TSTRIDE + c4 * 2) = hh;
        *(uint2*)(dst + 34816 + r * TSTRIDE + c4 * 2) = ll;
    }
}

// ============================================================
// Kernel P: LN(z) + 5 projections.  64 rows, 256 threads (8 warps, 2m x 4n), 2 CTAs/SM.
// smem: A_hi 0, A_lo 17408, WBUF0 34816 (36864), WBUF1 71680 (36864) = 108544.
// z staged via cp.async into WBUF1 (dead until phase-0 h1 load).
// ============================================================
#define PR_AHI 0u
#define PR_ALO 17408u
#define PR_WB0 34816u
#define PR_WB1 71680u
#define PR_SMEM 108544

__global__ void __launch_bounds__(256, 2) proj_kernel(
    const float* __restrict__ z, const float* __restrict__ gin, const float* __restrict__ bin,
    const float* __restrict__ bga, const float* __restrict__ bpa,
    const float* __restrict__ bgb, const float* __restrict__ bpb,
    const float* __restrict__ bog)
{
    extern __shared__ char smp[];
    const uint32_t sb = smem_u32(smp);
    const int tid = threadIdx.x, wid = tid >> 5, lane = tid & 31;

    const size_t m0 = (size_t)blockIdx.x * 64;
    const int b  = (int)(m0 >> 16);
    const int ii = (int)((m0 >> 8) & 255);
    const int k0 = (int)(m0 & 255);

    // async prefetch: z tile -> WB1 stage [64][128] f32, and wga.h0 -> WB0
    {
        const float* zsrc = z + m0 * 128;
        #pragma unroll
        for (int it = 0; it < 8; it++) {
            int lin = tid + it * 256;          // 0..2047 16B chunks
            int r = lin >> 5, c = lin & 31;
            cp16(sb + PR_WB1 + (uint32_t)r * 512u + (uint32_t)c * 16u, zsrc + r * 128 + c * 4);
        }
        cp_commit();
    }
    load_w_half(sb + PR_WB0, 0, 0);
    cp_wait0(); __syncthreads();

    {   // LN rows (from smem stage) -> split A tiles (8 rows per warp)
        const float* zs = (const float*)(smp + PR_WB1);
        const float g0 = gin[lane], g1 = gin[lane+32], g2 = gin[lane+64], g3 = gin[lane+96];
        const float c0 = bin[lane], c1 = bin[lane+32], c2 = bin[lane+64], c3 = bin[lane+96];
        #pragma unroll
        for (int r = 0; r < 8; r++) {
            int row = wid * 8 + r;
            ln_row(smp, PR_AHI, PR_ALO, row, lane, zs + row * 128,
                   g0, g1, g2, g3, c0, c1, c2, c3);
        }
    }
    __syncthreads();        // stage fully consumed before WB1 is overwritten

    const int m0w = (wid >> 2) * 32, n0w = (wid & 3) * 32;
    const uint32_t aH0 = sb + PR_AHI + (uint32_t)m0w * TSTRIDE;
    const uint32_t aL0 = sb + PR_ALO + (uint32_t)m0w * TSTRIDE;
    const uint32_t b0n = sb + PR_WB0 + (uint32_t)n0w * HSTRIDE;
    const uint32_t b1n = sb + PR_WB1 + (uint32_t)n0w * HSTRIDE;

    // ---- two gated-pair phases (invariant at entry: WB0 = (gmat, h0), no cp pending) ----
    for (int ph = 0; ph < 2; ph++) {
        const int gmat = ph ? 2 : 0, pmat = ph ? 3 : 1;
        const float* bg = ph ? bgb : bga;
        const float* bp = ph ? bpb : bpa;

        float accG[2][4][4] = {}, accP[2][4][4] = {};

        load_w_half(sb + PR_WB1, gmat, 1);
        gemm32<TSTRIDE, HSTRIDE>(accG, aH0, aL0, b0n, b0n + 18432u, lane);
        cp_wait0(); __syncthreads();

        load_w_half(sb + PR_WB0, pmat, 0);
        gemm32<TSTRIDE, HSTRIDE>(accG, aH0 + 128u, aL0 + 128u, b1n, b1n + 18432u, lane);
        cp_wait0(); __syncthreads();

        load_w_half(sb + PR_WB1, pmat, 1);
        gemm32<TSTRIDE, HSTRIDE>(accP, aH0, aL0, b0n, b0n + 18432u, lane);
        cp_wait0(); __syncthreads();

        gemm32<TSTRIDE, HSTRIDE>(accP, aH0 + 128u, aL0 + 128u, b1n, b1n + 18432u, lane);
        __syncthreads();

        // stage transposed into WBUF1: stH/stL [d 128][m 72] bf16
        uint16_t* stH = (uint16_t*)(smp + PR_WB1);
        uint16_t* stL = (uint16_t*)(smp + PR_WB1 + 18432u);
        #pragma unroll
        for (int mt = 0; mt < 2; mt++)
            #pragma unroll
            for (int q = 0; q < 4; q++) {
                int n = n0w + q * 8 + 2 * (lane & 3);
                float2 bg2 = *(const float2*)(bg + n);
                float2 bp2 = *(const float2*)(bp + n);
                #pragma unroll
                for (int rh = 0; rh < 2; rh++) {
                    int m = m0w + mt * 16 + (lane >> 2) + rh * 8;
                    float v0 = sigmoidf_(accG[mt][q][rh*2]   + bg2.x) * (accP[mt][q][rh*2]   + bp2.x);
                    float v1 = sigmoidf_(accG[mt][q][rh*2+1] + bg2.y) * (accP[mt][q][rh*2+1] + bp2.y);
                    uint16_t h0 = bf16bits(v0), h1 = bf16bits(v1);
                    stH[n * 72 + m]       = h0;  stL[n * 72 + m]       = bf16bits(v0 - bf2f(h0));
                    stH[(n + 1) * 72 + m] = h1;  stL[(n + 1) * 72 + m] = bf16bits(v1 - bf2f(h1));
                }
            }
        __syncthreads();

        load_w_half(sb + PR_WB0, ph ? 4 : 2, 0);    // next phase h0 — overlaps the store below

        __nv_bfloat16* dH = ph ? g_bt_hi : g_at_hi;
        __nv_bfloat16* dL = ph ? g_bt_lo : g_at_lo;
        #pragma unroll
        for (int it = 0; it < 8; it++) {
            int lin = tid + it * 256;               // 0..2047
            int hl  = lin >> 10;
            int idx = lin & 1023;
            int d = idx >> 3, m8 = (idx & 7) << 3;
            uint4 v = *(const uint4*)(smp + PR_WB1 + (uint32_t)hl * 18432u + d * HSTRIDE + m8 * 2);
            __nv_bfloat16* dst = hl ? dL : dH;
            *(uint4*)(dst + ((size_t)(b * 128 + d)) * 65536 + (size_t)ii * 256 + k0 + m8) = v;
        }
        cp_wait0(); __syncthreads();
    }

    // ---- gate phase (WB0 = wog h0) ----
    float acc[2][4][4] = {};
    load_w_half(sb + PR_WB1, 4, 1);
    gemm32<TSTRIDE, HSTRIDE>(acc, aH0, aL0, b0n, b0n + 18432u, lane);
    cp_wait0(); __syncthreads();
    gemm32<TSTRIDE, HSTRIDE>(acc, aH0 + 128u, aL0 + 128u, b1n, b1n + 18432u, lane);

    #pragma unroll
    for (int mt = 0; mt < 2; mt++)
        #pragma unroll
        for (int q = 0; q < 4; q++) {
            int n = n0w + q * 8 + 2 * (lane & 3);
            float2 bo2 = *(const float2*)(bog + n);
            #pragma unroll
            for (int rh = 0; rh < 2; rh++) {
                int m = m0w + mt * 16 + (lane >> 2) + rh * 8;
                float2 o;
                o.x = sigmoidf_(acc[mt][q][rh*2]   + bo2.x);
                o.y = sigmoidf_(acc[mt][q][rh*2+1] + bo2.y);
                *(float2*)(g_gate + (m0 + m) * 128 + n) = o;
            }
        }
}

// ============================================================
// Kernel T: triangle einsum. C tile 64x128, 256 threads (8 warps), 2 CTAs/SM.
// K = 256 in 4 chunks of 64, double-buffered (2 x 55296 = 110592 B).
// grid.x = 4096: bd = bx>>3, i0 = ((bx>>1)&3)*64, j0 = (bx&1)*128
// ============================================================
#define TR_BUFSZ 55296u
#define TR_SMEM  110592

__device__ __forceinline__ void tri_load_chunk(uint32_t bufBase, size_t base,
                                               int i0, int j0, int kc)
{
    #pragma unroll
    for (int it = 0; it < 12; it++) {
        int lin = threadIdx.x + it * 256;          // 0..3071
        if (lin < 1024) {                          // A: 64 rows, hi/lo
            int plane = lin >> 9, idx = lin & 511;
            int r = idx >> 3, c = idx & 7;
            const __nv_bfloat16* s = plane ? g_at_lo : g_at_hi;
            cp16(bufBase + (uint32_t)plane * 9216u + (uint32_t)r * HSTRIDE + (uint32_t)c * 16u,
                 s + base + (size_t)(i0 + r) * 256 + kc * 64 + c * 8);
        } else {                                   // B: 128 rows, hi/lo
            int l2 = lin - 1024;
            int plane = l2 >> 10, idx = l2 & 1023;
            int r = idx >> 3, c = idx & 7;
            const __nv_bfloat16* s = plane ? g_bt_lo : g_bt_hi;
            cp16(bufBase + 18432u + (uint32_t)plane * 18432u + (uint32_t)r * HSTRIDE + (uint32_t)c * 16u,
                 s + base + (size_t)(j0 + r) * 256 + kc * 64 + c * 8);
        }
    }
    cp_commit();
}

__global__ void __launch_bounds__(256, 2) tri_kernel()
{
    extern __shared__ char smp[];
    const uint32_t sb = smem_u32(smp);
    const int tid = threadIdx.x, wid = tid >> 5, lane = tid & 31;
    const int bx = blockIdx.x;
    const int bd = bx >> 3;
    const int i0 = ((bx >> 1) & 3) * 64;
    const int j0 = (bx & 1) * 128;
    const size_t base = (size_t)bd * 65536;

    const int m0w = (wid >> 2) * 32, n0w = (wid & 3) * 32;
    float acc[2][4][4] = {};

    tri_load_chunk(sb, base, i0, j0, 0);
    #pragma unroll
    for (int kc = 0; kc < 4; kc++) {
        cp_wait0(); __syncthreads();
        if (kc < 3) tri_load_chunk(sb + ((kc + 1) & 1) * TR_BUFSZ, base, i0, j0, kc + 1);
        const uint32_t bf = sb + (kc & 1) * TR_BUFSZ;
        gemm32<HSTRIDE, HSTRIDE>(acc,
            bf + (uint32_t)m0w * HSTRIDE, bf + 9216u + (uint32_t)m0w * HSTRIDE,
            bf + 18432u + (uint32_t)n0w * HSTRIDE, bf + 36864u + (uint32_t)n0w * HSTRIDE, lane);
    }

    #pragma unroll
    for (int mt = 0; mt < 2; mt++)
        #pragma unroll
        for (int q = 0; q < 4; q++) {
            int n = n0w + q * 8 + 2 * (lane & 3);
            #pragma unroll
            for (int rh = 0; rh < 2; rh++) {
                int m = m0w + mt * 16 + (lane >> 2) + rh * 8;
                float2 o = make_float2(acc[mt][q][rh*2], acc[mt][q][rh*2+1]);
                *(float2*)(g_ot + base + (size_t)(i0 + m) * 256 + j0 + n) = o;
            }
        }
}

// ============================================================
// Kernel F: async gather + column-LN + wop + gate.  64 p-rows, 256 threads, 3 CTAs/SM.
// smem: A_hi 0, A_lo 17408; S f32 [128 d][68] @34816 (34816 B, dead after LN);
//       W halves overlay S @34816 (36864).  Total 71680.
// grid.x = 4096: b = bx>>10, p0 = (bx&1023)*64
// ============================================================
#define FN_AHI 0u
#define FN_ALO 17408u
#define FN_S   34816u
#define FN_W   34816u
#define FN_SMEM 71680

__global__ void __launch_bounds__(256, 3) final_kernel(
    const float* __restrict__ gout, const float* __restrict__ bout,
    const float* __restrict__ bop, float* __restrict__ outp)
{
    extern __shared__ char smp[];
    const uint32_t sb = smem_u32(smp);
    const int tid = threadIdx.x, wid = tid >> 5, lane = tid & 31;
    const int b  = blockIdx.x >> 10;
    const int p0 = (blockIdx.x & 1023) * 64;

    // async raw gather: S[d][p] <- g_ot[b][d][p0 .. p0+63]  (d-major, coalesced)
    {
        const float* src = g_ot + (size_t)b * 128 * 65536 + p0;
        #pragma unroll
        for (int it = 0; it < 8; it++) {
            int lin = tid + it * 256;              // 0..2047 16B chunks
            int d = lin >> 4, c = lin & 15;
            cp16(sb + FN_S + (uint32_t)d * 272u + (uint32_t)c * 16u,
                 src + (size_t)d * 65536 + c * 4);
        }
        cp_commit();
    }
    cp_wait0(); __syncthreads();

    // column LN: warp w owns p = 8w..8w+7; 4 lanes per column (part = lane&3),
    // each lane covers d = part*32 + ((i + 2*part)&31)  (conflict-free banks).
    {
        const float* S = (const float*)(smp + FN_S);
        const int c  = lane >> 2, part = lane & 3;
        const int p  = wid * 8 + c;
        float s1 = 0.f;
        #pragma unroll
        for (int i = 0; i < 32; i++) {
            int d = part * 32 + ((i + 2 * part) & 31);
            s1 += S[d * 68 + p];
        }
        s1 += __shfl_xor_sync(0xffffffffu, s1, 1);
        s1 += __shfl_xor_sync(0xffffffffu, s1, 2);
        const float mean = s1 * (1.0f / 128.0f);
        float s2 = 0.f;
        #pragma unroll
        for (int i = 0; i < 32; i++) {
            int d = part * 32 + ((i + 2 * part) & 31);
            float v = S[d * 68 + p] - mean;
            s2 += v * v;
        }
        s2 += __shfl_xor_sync(0xffffffffu, s2, 1);
        s2 += __shfl_xor_sync(0xffffffffu, s2, 2);
        const float inv = rsqrtf(s2 * (1.0f / 128.0f) + 1e-5f);
        uint16_t* aH = (uint16_t*)(smp + FN_AHI);
        uint16_t* aL = (uint16_t*)(smp + FN_ALO);
        #pragma unroll
        for (int i = 0; i < 32; i++) {
            int d = part * 32 + ((i + 2 * part) & 31);
            float y = (S[d * 68 + p] - mean) * inv * gout[d] + bout[d];
            uint16_t h = bf16bits(y);
            aH[p * 136 + d] = h;
            aL[p * 136 + d] = bf16bits(y - bf2f(h));
        }
    }
    __syncthreads();            // S fully consumed before W overlays it

    const int m0w = (wid >> 2) * 32, n0w = (wid & 3) * 32;
    const uint32_t aH0 = sb + FN_AHI + (uint32_t)m0w * TSTRIDE;
    const uint32_t aL0 = sb + FN_ALO + (uint32_t)m0w * TSTRIDE;
    const uint32_t wn  = sb + FN_W + (uint32_t)n0w * HSTRIDE;

    float acc[2][4][4] = {};
    load_w_half(sb + FN_W, 5, 0);
    cp_wait0(); __syncthreads();
    gemm32<TSTRIDE, HSTRIDE>(acc, aH0, aL0, wn, wn + 18432u, lane);
    __syncthreads();
    load_w_half(sb + FN_W, 5, 1);
    cp_wait0(); __syncthreads();
    gemm32<TSTRIDE, HSTRIDE>(acc, aH0 + 128u, aL0 + 128u, wn, wn + 18432u, lane);

    #pragma unroll
    for (int mt = 0; mt < 2; mt++)
        #pragma unroll
        for (int q = 0; q < 4; q++) {
            int n = n0w + q * 8 + 2 * (lane & 3);
            float2 bo2 = *(const float2*)(bop + n);
            #pragma unroll
            for (int rh = 0; rh < 2; rh++) {
                int m = m0w + mt * 16 + (lane >> 2) + rh * 8;
                size_t gi = ((size_t)b * 65536 + p0 + m) * 128 + n;
                float2 g = *(const float2*)(g_gate + gi);
                float2 o;
                o.x = g.x * (acc[mt][q][rh*2]   + bo2.x);
                o.y = g.y * (acc[mt][q][rh*2+1] + bo2.y);
                *(float2*)(outp + gi) = o;
            }
        }
}

// ============================================================
// launch
// ============================================================
extern "C" void kernel_launch(void* const* d_in, const int* in_sizes, int n_in,
                              void* d_out, int out_size)
{
    const float* z    = (const float*)d_in[0];
    const float* gin  = (const float*)d_in[1];
    const float* bin  = (const float*)d_in[2];
    const float* wpa  = (const float*)d_in[3];
    const float* bpa  = (const float*)d_in[4];
    const float* wga  = (const float*)d_in[5];
    const float* bga  = (const float*)d_in[6];
    const float* wpb  = (const float*)d_in[7];
    const float* bpb  = (const float*)d_in[8];
    const float* wgb  = (const float*)d_in[9];
    const float* bgb  = (const float*)d_in[10];
    const float* gout = (const float*)d_in[11];
    const float* bout = (const float*)d_in[12];
    const float* wop  = (const float*)d_in[13];
    const float* bop  = (const float*)d_in[14];
    const float* wog  = (const float*)d_in[15];
    const float* bog  = (const float*)d_in[16];
    float* outp = (float*)d_out;

    cudaFuncSetAttribute(proj_kernel,  cudaFuncAttributeMaxDynamicSharedMemorySize, PR_SMEM);
    cudaFuncSetAttribute(tri_kernel,   cudaFuncAttributeMaxDynamicSharedMemorySize, TR_SMEM);
    cudaFuncSetAttribute(final_kernel, cudaFuncAttributeMaxDynamicSharedMemorySize, FN_SMEM);

    prep_w_kernel<<<6, 512>>>(wga, wpa, wgb, wpb, wog, wop);
    proj_kernel<<<4096, 256, PR_SMEM>>>(z, gin, bin, bga, bpa, bgb, bpb, bog);
    tri_kernel<<<4096, 256, TR_SMEM>>>();
    final_kernel<<<4096, 256, FN_SMEM>>>(gout, bout, bop, outp);
}

// round 12
// speedup vs baseline: 1.0675x; 1.0121x over previous
#include <cuda_runtime.h>
#include <cuda_bf16.h>
#include <cuda_fp16.h>
#include <stdint.h>

#define ELEMS ((size_t)4*256*256*128)   // 33.5M

// ---------------- scratch ----------------
__device__ __align__(16) __nv_bfloat16 g_at_hi[ELEMS];
__device__ __align__(16) __nv_bfloat16 g_at_lo[ELEMS];
__device__ __align__(16) __nv_bfloat16 g_bt_hi[ELEMS];
__device__ __align__(16) __nv_bfloat16 g_bt_lo[ELEMS];
__device__ __align__(16) __half g_gate[ELEMS];   // fp16: sigmoid in (0,1)
__device__ __align__(16) __half g_ot[ELEMS];     // fp16: LN-normalized downstream
// pre-split weight tile images: 6 mats x (hi 34816 B + lo 34816 B), 272 B row stride
__device__ __align__(16) unsigned char g_wt[6 * 69632];

// ---------------- helpers ----------------
__device__ __forceinline__ uint32_t smem_u32(const void* p){
    uint32_t a;
    asm("{ .reg .u64 t; cvta.to.shared.u64 t, %1; cvt.u32.u64 %0, t; }" : "=r"(a) : "l"(p));
    return a;
}
__device__ __forceinline__ void ldsm_x4(uint32_t* r, uint32_t a){
    asm volatile("ldmatrix.sync.aligned.m8n8.x4.shared.b16 {%0,%1,%2,%3}, [%4];"
        : "=r"(r[0]), "=r"(r[1]), "=r"(r[2]), "=r"(r[3]) : "r"(a));
}
__device__ __forceinline__ void mma16816(float* c, const uint32_t* a, const uint32_t* b){
    asm volatile("mma.sync.aligned.m16n8k16.row.col.f32.bf16.bf16.f32 "
        "{%0,%1,%2,%3}, {%4,%5,%6,%7}, {%8,%9}, {%0,%1,%2,%3};"
        : "+f"(c[0]), "+f"(c[1]), "+f"(c[2]), "+f"(c[3])
        : "r"(a[0]), "r"(a[1]), "r"(a[2]), "r"(a[3]), "r"(b[0]), "r"(b[1]));
}
__device__ __forceinline__ void cp16(uint32_t dst, const void* src){
    asm volatile("cp.async.cg.shared.global [%0], [%1], 16;" :: "r"(dst), "l"(src));
}
__device__ __forceinline__ void cp_commit(){
    asm volatile("cp.async.commit_group;" ::: "memory");
}
__device__ __forceinline__ void cp_wait0(){
    asm volatile("cp.async.wait_group 0;" ::: "memory");
}
__device__ __forceinline__ float sigmoidf_(float x){ return 1.0f / (1.0f + __expf(-x)); }
__device__ __forceinline__ uint16_t bf16bits(float v){
    __nv_bfloat16 h = __float2bfloat16(v);
    return *reinterpret_cast<uint16_t*>(&h);
}
__device__ __forceinline__ float bf2f(uint16_t u){
    __nv_bfloat16 h = *reinterpret_cast<__nv_bfloat16*>(&u);
    return __bfloat162float(h);
}
__device__ __forceinline__ void split4(float4 v, uint2& hh, uint2& ll){
    uint16_t h0=bf16bits(v.x), h1=bf16bits(v.y), h2=bf16bits(v.z), h3=bf16bits(v.w);
    uint16_t l0=bf16bits(v.x-bf2f(h0)), l1=bf16bits(v.y-bf2f(h1)),
             l2=bf16bits(v.z-bf2f(h2)), l3=bf16bits(v.w-bf2f(h3));
    hh.x = (uint32_t)h0 | ((uint32_t)h1<<16); hh.y = (uint32_t)h2 | ((uint32_t)h3<<16);
    ll.x = (uint32_t)l0 | ((uint32_t)l1<<16); ll.y = (uint32_t)l2 | ((uint32_t)l3<<16);
}

#define TSTRIDE 272u   // full-K (128) bf16 tile row stride in bytes
#define HSTRIDE 144u   // half-K (64)  bf16 tile row stride in bytes

// 32x32 warp-tile split GEMM over 64 K (4 ksteps). acc[2 m-subtiles][4 n-octets][4].
template<int SA, int SB>
__device__ __forceinline__ void gemm32(float (&acc)[2][4][4],
    uint32_t aHi, uint32_t aLo, uint32_t bHi, uint32_t bLo, int lane)
{
    const uint32_t aOff = (uint32_t)(lane & 15) * SA + (uint32_t)((lane >> 4) << 4);
    const uint32_t bOff = (uint32_t)(((lane >> 4) << 3) + (lane & 7)) * SB
                        + (uint32_t)(((lane >> 3) & 1) << 4);
    #pragma unroll
    for (int ks = 0; ks < 4; ks++) {
        const uint32_t ka = aOff + (uint32_t)ks * 32u;
        const uint32_t kb = bOff + (uint32_t)ks * 32u;
        uint32_t ah[2][4], al[2][4], bb[2][4];
        ldsm_x4(ah[0], aHi + ka);
        ldsm_x4(ah[1], aHi + 16u * SA + ka);
        ldsm_x4(bb[0], bHi + kb);
        ldsm_x4(bb[1], bHi + 16u * SB + kb);
        #pragma unroll
        for (int mt = 0; mt < 2; mt++)
            #pragma unroll
            for (int q = 0; q < 4; q++)
                mma16816(acc[mt][q], ah[mt], &bb[q >> 1][(q & 1) << 1]);
        ldsm_x4(al[0], aLo + ka);
        ldsm_x4(al[1], aLo + 16u * SA + ka);
        #pragma unroll
        for (int mt = 0; mt < 2; mt++)
            #pragma unroll
            for (int q = 0; q < 4; q++)
                mma16816(acc[mt][q], al[mt], &bb[q >> 1][(q & 1) << 1]);
        ldsm_x4(bb[0], bLo + kb);
        ldsm_x4(bb[1], bLo + 16u * SB + kb);
        #pragma unroll
        for (int mt = 0; mt < 2; mt++)
            #pragma unroll
            for (int q = 0; q < 4; q++)
                mma16816(acc[mt][q], ah[mt], &bb[q >> 1][(q & 1) << 1]);
    }
}

// async copy one half-K (64k) weight tile (hi + lo planes), 256-thread blocks
__device__ __forceinline__ void load_w_half(uint32_t dst, int mat, int half){
    const unsigned char* src = g_wt + (size_t)mat * 69632 + half * 128;
    #pragma unroll
    for (int it = 0; it < 8; it++) {
        int lin = threadIdx.x + it * 256;      // 0..2047
        int plane = lin >> 10, idx = lin & 1023;
        int r = idx >> 3, c = idx & 7;
        cp16(dst + (uint32_t)plane * 18432u + (uint32_t)r * HSTRIDE + (uint32_t)c * 16u,
             src + (size_t)plane * 34816 + (size_t)r * 272 + c * 16);
    }
    cp_commit();
}

// LN one row (128 cols) by a full warp; write split bf16 into A tile (272B stride).
__device__ __forceinline__ void ln_row(char* smp, uint32_t hiOff, uint32_t loOff,
    int row, int lane, const float* x,
    float g0, float g1, float g2, float g3,
    float c0, float c1, float c2, float c3)
{
    float v0 = x[lane], v1 = x[lane+32], v2 = x[lane+64], v3 = x[lane+96];
    float s = v0 + v1 + v2 + v3;
    #pragma unroll
    for (int o = 16; o > 0; o >>= 1) s += __shfl_xor_sync(0xffffffffu, s, o);
    float mean = s * (1.0f / 128.0f);
    float d0 = v0-mean, d1 = v1-mean, d2 = v2-mean, d3 = v3-mean;
    float q = d0*d0 + d1*d1 + d2*d2 + d3*d3;
    #pragma unroll
    for (int o = 16; o > 0; o >>= 1) q += __shfl_xor_sync(0xffffffffu, q, o);
    float inv = rsqrtf(q * (1.0f / 128.0f) + 1e-5f);
    float y0 = d0*inv*g0 + c0, y1 = d1*inv*g1 + c1;
    float y2 = d2*inv*g2 + c2, y3 = d3*inv*g3 + c3;
    uint16_t* aH = (uint16_t*)(smp + hiOff);
    uint16_t* aL = (uint16_t*)(smp + loOff);
    uint16_t h;
    h = bf16bits(y0); aH[row*136 + lane]      = h; aL[row*136 + lane]      = bf16bits(y0 - bf2f(h));
    h = bf16bits(y1); aH[row*136 + lane + 32] = h; aL[row*136 + lane + 32] = bf16bits(y1 - bf2f(h));
    h = bf16bits(y2); aH[row*136 + lane + 64] = h; aL[row*136 + lane + 64] = bf16bits(y2 - bf2f(h));
    h = bf16bits(y3); aH[row*136 + lane + 96] = h; aL[row*136 + lane + 96] = bf16bits(y3 - bf2f(h));
}

// ============================================================
// Kernel W: pre-split the 6 weight matrices (0=wga 1=wpa 2=wgb 3=wpb 4=wog 5=wop)
// ============================================================
__global__ void __launch_bounds__(512, 1) prep_w_kernel(
    const float* __restrict__ wga, const float* __restrict__ wpa,
    const float* __restrict__ wgb, const float* __restrict__ wpb,
    const float* __restrict__ wog, const float* __restrict__ wop)
{
    const float* Ws[6] = {wga, wpa, wgb, wpb, wog, wop};
    const float* W = Ws[blockIdx.x];
    unsigned char* dst = g_wt + (size_t)blockIdx.x * 69632;
    #pragma unroll
    for (int it = 0; it < 8; it++) {
        int lin = threadIdx.x + it * 512;
        int r = lin >> 5, c4 = (lin & 31) << 2;
        float4 v = *(const float4*)(W + r * 128 + c4);
        uint2 hh, ll;
        split4(v, hh, ll);
        *(uint2*)(dst + r * TSTRIDE + c4 * 2) = hh;
        *(uint2*)(dst + 34816 + r * TSTRIDE + c4 * 2) = ll;
    }
}

// ============================================================
// Kernel P: LN(z) + 5 projections.  64 rows, 256 threads (8 warps, 2m x 4n), 2 CTAs/SM.
// smem: A_hi 0, A_lo 17408, WBUF0 34816 (36864), WBUF1 71680 (36864) = 108544.
// z staged via cp.async into WBUF1 (dead until phase-0 h1 load).
// ============================================================
#define PR_AHI 0u
#define PR_ALO 17408u
#define PR_WB0 34816u
#define PR_WB1 71680u
#define PR_SMEM 108544

__global__ void __launch_bounds__(256, 2) proj_kernel(
    const float* __restrict__ z, const float* __restrict__ gin, const float* __restrict__ bin,
    const float* __restrict__ bga, const float* __restrict__ bpa,
    const float* __restrict__ bgb, const float* __restrict__ bpb,
    const float* __restrict__ bog)
{
    extern __shared__ char smp[];
    const uint32_t sb = smem_u32(smp);
    const int tid = threadIdx.x, wid = tid >> 5, lane = tid & 31;

    const size_t m0 = (size_t)blockIdx.x * 64;
    const int b  = (int)(m0 >> 16);
    const int ii = (int)((m0 >> 8) & 255);
    const int k0 = (int)(m0 & 255);

    // async prefetch: z tile -> WB1 stage [64][128] f32, and wga.h0 -> WB0
    {
        const float* zsrc = z + m0 * 128;
        #pragma unroll
        for (int it = 0; it < 8; it++) {
            int lin = tid + it * 256;          // 0..2047 16B chunks
            int r = lin >> 5, c = lin & 31;
            cp16(sb + PR_WB1 + (uint32_t)r * 512u + (uint32_t)c * 16u, zsrc + r * 128 + c * 4);
        }
        cp_commit();
    }
    load_w_half(sb + PR_WB0, 0, 0);
    cp_wait0(); __syncthreads();

    {   // LN rows (from smem stage) -> split A tiles (8 rows per warp)
        const float* zs = (const float*)(smp + PR_WB1);
        const float g0 = gin[lane], g1 = gin[lane+32], g2 = gin[lane+64], g3 = gin[lane+96];
        const float c0 = bin[lane], c1 = bin[lane+32], c2 = bin[lane+64], c3 = bin[lane+96];
        #pragma unroll
        for (int r = 0; r < 8; r++) {
            int row = wid * 8 + r;
            ln_row(smp, PR_AHI, PR_ALO, row, lane, zs + row * 128,
                   g0, g1, g2, g3, c0, c1, c2, c3);
        }
    }
    __syncthreads();        // stage fully consumed before WB1 is overwritten

    const int m0w = (wid >> 2) * 32, n0w = (wid & 3) * 32;
    const uint32_t aH0 = sb + PR_AHI + (uint32_t)m0w * TSTRIDE;
    const uint32_t aL0 = sb + PR_ALO + (uint32_t)m0w * TSTRIDE;
    const uint32_t b0n = sb + PR_WB0 + (uint32_t)n0w * HSTRIDE;
    const uint32_t b1n = sb + PR_WB1 + (uint32_t)n0w * HSTRIDE;

    // ---- two gated-pair phases (invariant at entry: WB0 = (gmat, h0), no cp pending) ----
    for (int ph = 0; ph < 2; ph++) {
        const int gmat = ph ? 2 : 0, pmat = ph ? 3 : 1;
        const float* bg = ph ? bgb : bga;
        const float* bp = ph ? bpb : bpa;

        float accG[2][4][4] = {}, accP[2][4][4] = {};

        load_w_half(sb + PR_WB1, gmat, 1);
        gemm32<TSTRIDE, HSTRIDE>(accG, aH0, aL0, b0n, b0n + 18432u, lane);
        cp_wait0(); __syncthreads();

        load_w_half(sb + PR_WB0, pmat, 0);
        gemm32<TSTRIDE, HSTRIDE>(accG, aH0 + 128u, aL0 + 128u, b1n, b1n + 18432u, lane);
        cp_wait0(); __syncthreads();

        load_w_half(sb + PR_WB1, pmat, 1);
        gemm32<TSTRIDE, HSTRIDE>(accP, aH0, aL0, b0n, b0n + 18432u, lane);
        cp_wait0(); __syncthreads();

        gemm32<TSTRIDE, HSTRIDE>(accP, aH0 + 128u, aL0 + 128u, b1n, b1n + 18432u, lane);
        __syncthreads();

        // stage transposed into WBUF1: stH/stL [d 128][m 72] bf16
        uint16_t* stH = (uint16_t*)(smp + PR_WB1);
        uint16_t* stL = (uint16_t*)(smp + PR_WB1 + 18432u);
        #pragma unroll
        for (int mt = 0; mt < 2; mt++)
            #pragma unroll
            for (int q = 0; q < 4; q++) {
                int n = n0w + q * 8 + 2 * (lane & 3);
                float2 bg2 = *(const float2*)(bg + n);
                float2 bp2 = *(const float2*)(bp + n);
                #pragma unroll
                for (int rh = 0; rh < 2; rh++) {
                    int m = m0w + mt * 16 + (lane >> 2) + rh * 8;
                    float v0 = sigmoidf_(accG[mt][q][rh*2]   + bg2.x) * (accP[mt][q][rh*2]   + bp2.x);
                    float v1 = sigmoidf_(accG[mt][q][rh*2+1] + bg2.y) * (accP[mt][q][rh*2+1] + bp2.y);
                    uint16_t h0 = bf16bits(v0), h1 = bf16bits(v1);
                    stH[n * 72 + m]       = h0;  stL[n * 72 + m]       = bf16bits(v0 - bf2f(h0));
                    stH[(n + 1) * 72 + m] = h1;  stL[(n + 1) * 72 + m] = bf16bits(v1 - bf2f(h1));
                }
            }
        __syncthreads();

        load_w_half(sb + PR_WB0, ph ? 4 : 2, 0);    // next phase h0 — overlaps the store below

        __nv_bfloat16* dH = ph ? g_bt_hi : g_at_hi;
        __nv_bfloat16* dL = ph ? g_bt_lo : g_at_lo;
        #pragma unroll
        for (int it = 0; it < 8; it++) {
            int lin = tid + it * 256;               // 0..2047
            int hl  = lin >> 10;
            int idx = lin & 1023;
            int d = idx >> 3, m8 = (idx & 7) << 3;
            uint4 v = *(const uint4*)(smp + PR_WB1 + (uint32_t)hl * 18432u + d * HSTRIDE + m8 * 2);
            __nv_bfloat16* dst = hl ? dL : dH;
            *(uint4*)(dst + ((size_t)(b * 128 + d)) * 65536 + (size_t)ii * 256 + k0 + m8) = v;
        }
        cp_wait0(); __syncthreads();
    }

    // ---- gate phase (WB0 = wog h0) ----
    float acc[2][4][4] = {};
    load_w_half(sb + PR_WB1, 4, 1);
    gemm32<TSTRIDE, HSTRIDE>(acc, aH0, aL0, b0n, b0n + 18432u, lane);
    cp_wait0(); __syncthreads();
    gemm32<TSTRIDE, HSTRIDE>(acc, aH0 + 128u, aL0 + 128u, b1n, b1n + 18432u, lane);

    #pragma unroll
    for (int mt = 0; mt < 2; mt++)
        #pragma unroll
        for (int q = 0; q < 4; q++) {
            int n = n0w + q * 8 + 2 * (lane & 3);
            float2 bo2 = *(const float2*)(bog + n);
            #pragma unroll
            for (int rh = 0; rh < 2; rh++) {
                int m = m0w + mt * 16 + (lane >> 2) + rh * 8;
                __half2 o = __floats2half2_rn(sigmoidf_(acc[mt][q][rh*2]   + bo2.x),
                                              sigmoidf_(acc[mt][q][rh*2+1] + bo2.y));
                *(__half2*)(g_gate + (m0 + m) * 128 + n) = o;
            }
        }
}

// ============================================================
// Kernel T: triangle einsum. C tile 64x128, 256 threads (8 warps), 2 CTAs/SM.
// K = 256 in 4 chunks of 64, double-buffered (2 x 55296 = 110592 B).
// grid.x = 4096: bd = bx>>3, i0 = ((bx>>1)&3)*64, j0 = (bx&1)*128
// Output g_ot stored as fp16.
// ============================================================
#define TR_BUFSZ 55296u
#define TR_SMEM  110592

__device__ __forceinline__ void tri_load_chunk(uint32_t bufBase, size_t base,
                                               int i0, int j0, int kc)
{
    #pragma unroll
    for (int it = 0; it < 12; it++) {
        int lin = threadIdx.x + it * 256;          // 0..3071
        if (lin < 1024) {                          // A: 64 rows, hi/lo
            int plane = lin >> 9, idx = lin & 511;
            int r = idx >> 3, c = idx & 7;
            const __nv_bfloat16* s = plane ? g_at_lo : g_at_hi;
            cp16(bufBase + (uint32_t)plane * 9216u + (uint32_t)r * HSTRIDE + (uint32_t)c * 16u,
                 s + base + (size_t)(i0 + r) * 256 + kc * 64 + c * 8);
        } else {                                   // B: 128 rows, hi/lo
            int l2 = lin - 1024;
            int plane = l2 >> 10, idx = l2 & 1023;
            int r = idx >> 3, c = idx & 7;
            const __nv_bfloat16* s = plane ? g_bt_lo : g_bt_hi;
            cp16(bufBase + 18432u + (uint32_t)plane * 18432u + (uint32_t)r * HSTRIDE + (uint32_t)c * 16u,
                 s + base + (size_t)(j0 + r) * 256 + kc * 64 + c * 8);
        }
    }
    cp_commit();
}

__global__ void __launch_bounds__(256, 2) tri_kernel()
{
    extern __shared__ char smp[];
    const uint32_t sb = smem_u32(smp);
    const int tid = threadIdx.x, wid = tid >> 5, lane = tid & 31;
    const int bx = blockIdx.x;
    const int bd = bx >> 3;
    const int i0 = ((bx >> 1) & 3) * 64;
    const int j0 = (bx & 1) * 128;
    const size_t base = (size_t)bd * 65536;

    const int m0w = (wid >> 2) * 32, n0w = (wid & 3) * 32;
    float acc[2][4][4] = {};

    tri_load_chunk(sb, base, i0, j0, 0);
    #pragma unroll
    for (int kc = 0; kc < 4; kc++) {
        cp_wait0(); __syncthreads();
        if (kc < 3) tri_load_chunk(sb + ((kc + 1) & 1) * TR_BUFSZ, base, i0, j0, kc + 1);
        const uint32_t bf = sb + (kc & 1) * TR_BUFSZ;
        gemm32<HSTRIDE, HSTRIDE>(acc,
            bf + (uint32_t)m0w * HSTRIDE, bf + 9216u + (uint32_t)m0w * HSTRIDE,
            bf + 18432u + (uint32_t)n0w * HSTRIDE, bf + 36864u + (uint32_t)n0w * HSTRIDE, lane);
    }

    #pragma unroll
    for (int mt = 0; mt < 2; mt++)
        #pragma unroll
        for (int q = 0; q < 4; q++) {
            int n = n0w + q * 8 + 2 * (lane & 3);
            #pragma unroll
            for (int rh = 0; rh < 2; rh++) {
                int m = m0w + mt * 16 + (lane >> 2) + rh * 8;
                __half2 o = __floats2half2_rn(acc[mt][q][rh*2], acc[mt][q][rh*2+1]);
                *(__half2*)(g_ot + base + (size_t)(i0 + m) * 256 + j0 + n) = o;
            }
        }
}

// ============================================================
// Kernel F: async gather + column-LN + wop + gate.  64 p-rows, 256 threads, 3 CTAs/SM.
// smem: A_hi 0, A_lo 17408; S fp16 [128 d][72] @34816 (18432 B, dead after LN);
//       W halves overlay S @34816 (36864).  Total 71680.
// grid.x = 4096: b = bx>>10, p0 = (bx&1023)*64
// ============================================================
#define FN_AHI 0u
#define FN_ALO 17408u
#define FN_S   34816u
#define FN_W   34816u
#define FN_SMEM 71680

__global__ void __launch_bounds__(256, 3) final_kernel(
    const float* __restrict__ gout, const float* __restrict__ bout,
    const float* __restrict__ bop, float* __restrict__ outp)
{
    extern __shared__ char smp[];
    const uint32_t sb = smem_u32(smp);
    const int tid = threadIdx.x, wid = tid >> 5, lane = tid & 31;
    const int b  = blockIdx.x >> 10;
    const int p0 = (blockIdx.x & 1023) * 64;

    // async raw gather: S[d][p] <- g_ot[b][d][p0 .. p0+63] fp16 (d-major, coalesced)
    {
        const __half* src = g_ot + (size_t)b * 128 * 65536 + p0;
        #pragma unroll
        for (int it = 0; it < 4; it++) {
            int lin = tid + it * 256;              // 0..1023 16B chunks
            int d = lin >> 3, c = lin & 7;
            cp16(sb + FN_S + (uint32_t)d * 144u + (uint32_t)c * 16u,
                 src + (size_t)d * 65536 + c * 8);
        }
        cp_commit();
    }
    cp_wait0(); __syncthreads();

    // column LN: warp w owns p = 8w..8w+7; 4 lanes per column (part = lane&3),
    // each lane covers d = part*32 + ((i + 2*part)&31).
    {
        const __half* S = (const __half*)(smp + FN_S);
        const int c  = lane >> 2, part = lane & 3;
        const int p  = wid * 8 + c;
        float s1 = 0.f;
        #pragma unroll
        for (int i = 0; i < 32; i++) {
            int d = part * 32 + ((i + 2 * part) & 31);
            s1 += __half2float(S[d * 72 + p]);
        }
        s1 += __shfl_xor_sync(0xffffffffu, s1, 1);
        s1 += __shfl_xor_sync(0xffffffffu, s1, 2);
        const float mean = s1 * (1.0f / 128.0f);
        float s2 = 0.f;
        #pragma unroll
        for (int i = 0; i < 32; i++) {
            int d = part * 32 + ((i + 2 * part) & 31);
            float v = __half2float(S[d * 72 + p]) - mean;
            s2 += v * v;
        }
        s2 += __shfl_xor_sync(0xffffffffu, s2, 1);
        s2 += __shfl_xor_sync(0xffffffffu, s2, 2);
        const float inv = rsqrtf(s2 * (1.0f / 128.0f) + 1e-5f);
        uint16_t* aH = (uint16_t*)(smp + FN_AHI);
        uint16_t* aL = (uint16_t*)(smp + FN_ALO);
        #pragma unroll
        for (int i = 0; i < 32; i++) {
            int d = part * 32 + ((i + 2 * part) & 31);
            float y = (__half2float(S[d * 72 + p]) - mean) * inv * gout[d] + bout[d];
            uint16_t h = bf16bits(y);
            aH[p * 136 + d] = h;
            aL[p * 136 + d] = bf16bits(y - bf2f(h));
        }
    }
    __syncthreads();            // S fully consumed before W overlays it

    const int m0w = (wid >> 2) * 32, n0w = (wid & 3) * 32;
    const uint32_t aH0 = sb + FN_AHI + (uint32_t)m0w * TSTRIDE;
    const uint32_t aL0 = sb + FN_ALO + (uint32_t)m0w * TSTRIDE;
    const uint32_t wn  = sb + FN_W + (uint32_t)n0w * HSTRIDE;

    float acc[2][4][4] = {};
    load_w_half(sb + FN_W, 5, 0);
    cp_wait0(); __syncthreads();
    gemm32<TSTRIDE, HSTRIDE>(acc, aH0, aL0, wn, wn + 18432u, lane);
    __syncthreads();
    load_w_half(sb + FN_W, 5, 1);
    cp_wait0(); __syncthreads();
    gemm32<TSTRIDE, HSTRIDE>(acc, aH0 + 128u, aL0 + 128u, wn, wn + 18432u, lane);

    #pragma unroll
    for (int mt = 0; mt < 2; mt++)
        #pragma unroll
        for (int q = 0; q < 4; q++) {
            int n = n0w + q * 8 + 2 * (lane & 3);
            float2 bo2 = *(const float2*)(bop + n);
            #pragma unroll
            for (int rh = 0; rh < 2; rh++) {
                int m = m0w + mt * 16 + (lane >> 2) + rh * 8;
                size_t gi = ((size_t)b * 65536 + p0 + m) * 128 + n;
                float2 g = __half22float2(*(const __half2*)(g_gate + gi));
                float2 o;
                o.x = g.x * (acc[mt][q][rh*2]   + bo2.x);
                o.y = g.y * (acc[mt][q][rh*2+1] + bo2.y);
                *(float2*)(outp + gi) = o;
            }
        }
}

// ============================================================
// launch
// ============================================================
extern "C" void kernel_launch(void* const* d_in, const int* in_sizes, int n_in,
                              void* d_out, int out_size)
{
    const float* z    = (const float*)d_in[0];
    const float* gin  = (const float*)d_in[1];
    const float* bin  = (const float*)d_in[2];
    const float* wpa  = (const float*)d_in[3];
    const float* bpa  = (const float*)d_in[4];
    const float* wga  = (const float*)d_in[5];
    const float* bga  = (const float*)d_in[6];
    const float* wpb  = (const float*)d_in[7];
    const float* bpb  = (const float*)d_in[8];
    const float* wgb  = (const float*)d_in[9];
    const float* bgb  = (const float*)d_in[10];
    const float* gout = (const float*)d_in[11];
    const float* bout = (const float*)d_in[12];
    const float* wop  = (const float*)d_in[13];
    const float* bop  = (const float*)d_in[14];
    const float* wog  = (const float*)d_in[15];
    const float* bog  = (const float*)d_in[16];
    float* outp = (float*)d_out;

    cudaFuncSetAttribute(proj_kernel,  cudaFuncAttributeMaxDynamicSharedMemorySize, PR_SMEM);
    cudaFuncSetAttribute(tri_kernel,   cudaFuncAttributeMaxDynamicSharedMemorySize, TR_SMEM);
    cudaFuncSetAttribute(final_kernel, cudaFuncAttributeMaxDynamicSharedMemorySize, FN_SMEM);

    prep_w_kernel<<<6, 512>>>(wga, wpa, wgb, wpb, wog, wop);
    proj_kernel<<<4096, 256, PR_SMEM>>>(z, gin, bin, bga, bpa, bgb, bpb, bog);
    tri_kernel<<<4096, 256, TR_SMEM>>>();
    final_kernel<<<4096, 256, FN_SMEM>>>(gout, bout, bop, outp);
}